// round 1
// baseline (speedup 1.0000x reference)
#include <cuda_runtime.h>
#include <math.h>

#define STEPS 2048
#define BATCH 512
#define HID   128
#define OUTJ  89      // 9 (W_in) + 80 (W_out)
#define SPB   4       // samples per block
#define NBLK  (BATCH / SPB)   // 128 blocks -> one wave on 148 SMs

__device__ float g_baseflow[BATCH];

// ---------------------------------------------------------------------------
// Kernel 1: per-batch-element 25th percentile of flow over 2048 steps
// (bitonic sort in shared memory; linear interpolation like jnp.percentile)
// ---------------------------------------------------------------------------
__global__ void baseflow_kernel(const float* __restrict__ hyd) {
    __shared__ float v[STEPS];
    const int b = blockIdx.x;
    const int tid = threadIdx.x;
    for (int t = tid; t < STEPS; t += blockDim.x)
        v[t] = hyd[(t * BATCH + b) * 17];   // feature 0 = flow
    __syncthreads();
    for (int k = 2; k <= STEPS; k <<= 1) {
        for (int j = k >> 1; j > 0; j >>= 1) {
            for (int i = tid; i < STEPS; i += blockDim.x) {
                int l = i ^ j;
                if (l > i) {
                    float a = v[i], c = v[l];
                    bool up = ((i & k) == 0);
                    if ((a > c) == up) { v[i] = c; v[l] = a; }
                }
            }
            __syncthreads();
        }
    }
    // pos = 0.25*(2048-1) = 511.75 -> 0.25*s[511] + 0.75*s[512]
    if (tid == 0)
        g_baseflow[b] = 0.25f * v[511] + 0.75f * v[512];
}

// ---------------------------------------------------------------------------
// Shared-memory layout for the main kernel (~128 KB -> 1 block/SM)
// ---------------------------------------------------------------------------
struct __align__(16) Smem {
    float w0t[24 * 128];        // W0 transposed: [i][j]
    float w1t[128 * 128];       // W1 transposed
    float wct[128 * OUTJ];      // [W_in; W_out] transposed: [i][j], j<9 -> W_in
    float b0s[128];
    float b1s[128];
    float bcs[92];              // padded to 4-float multiple
    float xin[24 * 4];          // [i][sample]
    float hA[128 * 4];
    float hB[128 * 4];
    float outb[4 * 92];         // [sample][j]
    float st[4 * 8];            // stores state per sample
    float rain_s[4];
    float bflow_s[4];
};

// ---------------------------------------------------------------------------
// Kernel 2: the 2048-step recurrence. 128 threads = 4 warps; warp w owns
// sample blk*4+w for the scalar epilogue; all 128 threads cooperate on the
// three matvec layers (thread j = hidden/output unit j, 4 samples at once).
// ---------------------------------------------------------------------------
__global__ void __launch_bounds__(128, 1)
hyd_kernel(const float* __restrict__ hyd,
           const float* __restrict__ W0, const float* __restrict__ b0,
           const float* __restrict__ W1, const float* __restrict__ b1,
           const float* __restrict__ Wi, const float* __restrict__ bi,
           const float* __restrict__ Wo, const float* __restrict__ bo,
           float* __restrict__ out)
{
    extern __shared__ char raw[];
    Smem* S = (Smem*)raw;
    const int tid  = threadIdx.x;
    const int wid  = tid >> 5;
    const int lane = tid & 31;
    const int blk  = blockIdx.x;
    const int b    = blk * SPB + wid;      // this warp's sample

    // ---- load + transpose weights into SMEM (once) ----
    for (int idx = tid; idx < 24 * 128; idx += 128) {
        int i = idx >> 7, j = idx & 127;
        S->w0t[idx] = W0[j * 24 + i];
    }
    for (int idx = tid; idx < 128 * 128; idx += 128) {
        int i = idx >> 7, j = idx & 127;
        S->w1t[idx] = W1[j * 128 + i];
    }
    for (int idx = tid; idx < 128 * OUTJ; idx += 128) {
        int i = idx / OUTJ, j = idx % OUTJ;
        S->wct[idx] = (j < 9) ? Wi[j * 128 + i] : Wo[(j - 9) * 128 + i];
    }
    S->b0s[tid] = b0[tid];
    S->b1s[tid] = b1[tid];
    if (tid < OUTJ) S->bcs[tid] = (tid < 9) ? bi[tid] : bo[tid - 9];
    if (tid < 32) { int k = tid & 7; S->st[tid] = (k == 1) ? 1.0f : 0.0f; }
    if (tid < SPB) S->bflow_s[tid] = g_baseflow[blk * SPB + tid];
    __syncthreads();

    // prefetch x for t=0 (lanes 0..15 hold the 16 features of this sample)
    float xreg = 0.0f;
    if (lane < 16) xreg = hyd[b * 17 + 1 + lane];

    for (int t = 0; t < STEPS; t++) {
        // ---- build layer-0 input [x_t, 0.01*stores] ----
        if (lane < 16)      S->xin[lane * 4 + wid] = xreg;
        else if (lane < 24) S->xin[lane * 4 + wid] = 0.01f * S->st[wid * 8 + (lane - 16)];
        if (lane == 0)      S->rain_s[wid] = xreg;   // rain = feature 0
        __syncthreads();

        // prefetch next step's x (overlaps the ~2K-cycle step compute)
        if (lane < 16 && t + 1 < STEPS)
            xreg = hyd[((t + 1) * BATCH + b) * 17 + 1 + lane];

        // ---- layer 0: 24 -> 128, relu ----
        float a0, a1, a2, a3;
        a0 = a1 = a2 = a3 = S->b0s[tid];
        #pragma unroll
        for (int i = 0; i < 24; i++) {
            float  w  = S->w0t[i * 128 + tid];
            float4 h4 = *(const float4*)&S->xin[i * 4];
            a0 = fmaf(h4.x, w, a0); a1 = fmaf(h4.y, w, a1);
            a2 = fmaf(h4.z, w, a2); a3 = fmaf(h4.w, w, a3);
        }
        float4 hv;
        hv.x = fmaxf(a0, 0.f); hv.y = fmaxf(a1, 0.f);
        hv.z = fmaxf(a2, 0.f); hv.w = fmaxf(a3, 0.f);
        *(float4*)&S->hA[tid * 4] = hv;
        __syncthreads();

        // ---- layer 1: 128 -> 128, relu ----
        a0 = a1 = a2 = a3 = S->b1s[tid];
        #pragma unroll 16
        for (int i = 0; i < 128; i++) {
            float  w  = S->w1t[i * 128 + tid];
            float4 h4 = *(const float4*)&S->hA[i * 4];
            a0 = fmaf(h4.x, w, a0); a1 = fmaf(h4.y, w, a1);
            a2 = fmaf(h4.z, w, a2); a3 = fmaf(h4.w, w, a3);
        }
        hv.x = fmaxf(a0, 0.f); hv.y = fmaxf(a1, 0.f);
        hv.z = fmaxf(a2, 0.f); hv.w = fmaxf(a3, 0.f);
        *(float4*)&S->hB[tid * 4] = hv;
        __syncthreads();

        // ---- output layer: 128 -> 89 (9 logits + 80 gate pre-acts) ----
        if (tid < OUTJ) {
            a0 = a1 = a2 = a3 = S->bcs[tid];
            #pragma unroll 16
            for (int i = 0; i < 128; i++) {
                float  w  = S->wct[i * OUTJ + tid];
                float4 h4 = *(const float4*)&S->hB[i * 4];
                a0 = fmaf(h4.x, w, a0); a1 = fmaf(h4.y, w, a1);
                a2 = fmaf(h4.z, w, a2); a3 = fmaf(h4.w, w, a3);
            }
            S->outb[0 * 92 + tid] = a0;
            S->outb[1 * 92 + tid] = a1;
            S->outb[2 * 92 + tid] = a2;
            S->outb[3 * 92 + tid] = a3;
        }
        __syncthreads();

        // ---- epilogue: warp wid handles its own sample ----
        {
            float* o   = &S->outb[wid * 92];
            float* stp = &S->st[wid * 8];

            // softmax over o[0..8]
            float logit = (lane < 9) ? o[lane] : -1e30f;
            float m = logit;
            #pragma unroll
            for (int off = 16; off > 0; off >>= 1)
                m = fmaxf(m, __shfl_xor_sync(0xffffffffu, m, off));
            float e = (lane < 9) ? expf(logit - m) : 0.f;
            float ssum = e;
            #pragma unroll
            for (int off = 16; off > 0; off >>= 1)
                ssum += __shfl_xor_sync(0xffffffffu, ssum, off);
            float aval = e / ssum;

            // stores += a[1:] * rain
            float rain = S->rain_s[wid];
            if (lane >= 1 && lane < 9)
                stp[lane - 1] += aval * rain;

            // sigmoid over the 80 gate values, in place (warp-parallel)
            #pragma unroll
            for (int r = 0; r < 3; r++) {
                int idx = lane + 32 * r;
                if (idx < 80) {
                    float v = o[9 + idx];
                    o[9 + idx] = 1.0f / (1.0f + expf(-v));
                }
            }
            __syncwarp();

            // serial mixing / escape / flow in lane 0 (tiny, register-resident)
            if (lane == 0) {
                const float* bb = o + 9;
                float sv[8];
                #pragma unroll
                for (int k = 0; k < 8; k++) sv[k] = stp[k];
                #pragma unroll
                for (int d = 0; d < 8; d++) {
                    float fb[8]; float fsum = 0.f;
                    #pragma unroll
                    for (int k = 0; k < 8; k++) { fb[k] = bb[d * 8 + k] * sv[k]; fsum += fb[k]; }
                    #pragma unroll
                    for (int k = 0; k < 8; k++) sv[k] -= fb[k];
                    sv[d] += fsum;
                }
                #pragma unroll
                for (int k = 0; k < 8; k++) sv[k] -= bb[64 + k] * sv[k];   // escape
                float flow = 0.f;
                #pragma unroll
                for (int k = 0; k < 8; k++) {
                    float fd = bb[72 + k] * sv[k];
                    flow += fd;
                    sv[k] -= fd;
                }
                out[t * BATCH + b] = flow;
                if (t == 0)
                    sv[2] = S->bflow_s[wid] / fmaxf(bb[74], 1e-5f);  // bb[74]=b_flow[SLOW]
                #pragma unroll
                for (int k = 0; k < 8; k++) stp[k] = sv[k];
            }
        }
        __syncthreads();   // stores visible for next step's input build
    }
}

// ---------------------------------------------------------------------------
// Harness entry
// Input order (metadata): hyd_input, W0, b0, W1, b1, W_in, b_in, W_out, b_out
// ---------------------------------------------------------------------------
extern "C" void kernel_launch(void* const* d_in, const int* in_sizes, int n_in,
                              void* d_out, int out_size) {
    const float* hyd = (const float*)d_in[0];
    const float* W0  = (const float*)d_in[1];
    const float* b0  = (const float*)d_in[2];
    const float* W1  = (const float*)d_in[3];
    const float* b1  = (const float*)d_in[4];
    const float* Wi  = (const float*)d_in[5];
    const float* bi  = (const float*)d_in[6];
    const float* Wo  = (const float*)d_in[7];
    const float* bo  = (const float*)d_in[8];
    float* out = (float*)d_out;

    cudaFuncSetAttribute(hyd_kernel,
                         cudaFuncAttributeMaxDynamicSharedMemorySize,
                         (int)sizeof(Smem));

    baseflow_kernel<<<BATCH, 256>>>(hyd);
    hyd_kernel<<<NBLK, 128, sizeof(Smem)>>>(hyd, W0, b0, W1, b1, Wi, bi, Wo, bo, out);
}

// round 2
// speedup vs baseline: 2.2130x; 2.2130x over previous
#include <cuda_runtime.h>
#include <math.h>

#define STEPS 2048
#define BATCH 512
#define SPB   4
#define NBLK  (BATCH / SPB)   // 128 blocks -> one wave on 148 SMs
#define THREADS 256

typedef unsigned long long u64;

__device__ float g_baseflow[BATCH];

// ---------------------------------------------------------------------------
// packed f32x2 helpers
// ---------------------------------------------------------------------------
__device__ __forceinline__ u64 pack2(float lo, float hi) {
    u64 r; asm("mov.b64 %0, {%1, %2};" : "=l"(r) : "f"(lo), "f"(hi)); return r;
}
__device__ __forceinline__ void unpack2(u64 v, float& lo, float& hi) {
    asm("mov.b64 {%0, %1}, %2;" : "=f"(lo), "=f"(hi) : "l"(v));
}
__device__ __forceinline__ void fma2(u64& acc, u64 a, u64 b) {
    asm("fma.rn.f32x2 %0, %1, %2, %0;" : "+l"(acc) : "l"(a), "l"(b));
}
__device__ __forceinline__ u64 add2(u64 a, u64 b) {
    u64 r; asm("add.rn.f32x2 %0, %1, %2;" : "=l"(r) : "l"(a), "l"(b)); return r;
}

// ---------------------------------------------------------------------------
// Kernel 1: per-batch-element 25th percentile of flow (bitonic sort)
// ---------------------------------------------------------------------------
__global__ void baseflow_kernel(const float* __restrict__ hyd) {
    __shared__ float v[STEPS];
    const int b = blockIdx.x;
    const int tid = threadIdx.x;
    for (int t = tid; t < STEPS; t += blockDim.x)
        v[t] = hyd[(t * BATCH + b) * 17];
    __syncthreads();
    for (int k = 2; k <= STEPS; k <<= 1) {
        for (int j = k >> 1; j > 0; j >>= 1) {
            for (int i = tid; i < STEPS; i += blockDim.x) {
                int l = i ^ j;
                if (l > i) {
                    float a = v[i], c = v[l];
                    bool up = ((i & k) == 0);
                    if ((a > c) == up) { v[i] = c; v[l] = a; }
                }
            }
            __syncthreads();
        }
    }
    if (tid == 0)
        g_baseflow[b] = 0.25f * v[511] + 0.75f * v[512];   // pos = 511.75
}

// ---------------------------------------------------------------------------
// Shared memory (static, ~24 KB)
// ---------------------------------------------------------------------------
struct __align__(16) Smem {
    float w0t[24 * 128];        // W0 transposed [i][j]
    float b0s[128];
    float b1s[128];
    float bcs[96];              // combined bias [W_in;W_out], padded
    float xin[24 * 4];          // layer-0 input [i][sample]
    float hA[128 * 4];          // layer-0 output
    float hB[128 * 4];          // layer-1 output
    float part[2][128][4];      // reduction-split partials [half][j][sample]
    float outg[4][80];          // sigmoided gates per sample
    float st[4 * 8];            // stores state
    float rain_s[4];
    float bflow_s[4];
};

// ---------------------------------------------------------------------------
// Kernel 2: the 2048-step recurrence.
// 256 threads = 8 warps (2/SMSP). j = tid&127 owns hidden/output unit j;
// half = tid>>7 owns half of the reduction dim for layers 1 and 2.
// Warps 0-3: warp w also owns sample blk*4+w for input build + epilogue.
// W1 / W_out columns live in registers (loaded once, reused 2048 steps).
// ---------------------------------------------------------------------------
__global__ void __launch_bounds__(THREADS, 1)
hyd_kernel(const float* __restrict__ hyd,
           const float* __restrict__ W0, const float* __restrict__ b0,
           const float* __restrict__ W1, const float* __restrict__ b1,
           const float* __restrict__ Wi, const float* __restrict__ bi,
           const float* __restrict__ Wo, const float* __restrict__ bo,
           float* __restrict__ out)
{
    __shared__ Smem S;
    const int tid  = threadIdx.x;
    const int j    = tid & 127;
    const int half = tid >> 7;
    const int lane = tid & 31;
    const int wid4 = (tid >> 5) & 3;   // sample index for tid<128
    const int blk  = blockIdx.x;

    // ---- register-resident weight columns ----
    float w1r[64], wcr[64];
    #pragma unroll
    for (int k = 0; k < 64; k++) w1r[k] = W1[j * 128 + half * 64 + k];
    if (j < 9) {
        #pragma unroll
        for (int k = 0; k < 64; k++) wcr[k] = Wi[j * 128 + half * 64 + k];
    } else if (j < 89) {
        #pragma unroll
        for (int k = 0; k < 64; k++) wcr[k] = Wo[(j - 9) * 128 + half * 64 + k];
    } else {
        #pragma unroll
        for (int k = 0; k < 64; k++) wcr[k] = 0.f;
    }

    // ---- SMEM init ----
    for (int idx = tid; idx < 24 * 128; idx += THREADS) {
        int i = idx >> 7, jj = idx & 127;
        S.w0t[idx] = W0[jj * 24 + i];
    }
    if (tid < 128) { S.b0s[tid] = b0[tid]; S.b1s[tid] = b1[tid]; }
    if (tid < 89)  S.bcs[tid] = (tid < 9) ? bi[tid] : bo[tid - 9];
    if (tid < 32)  S.st[tid] = ((tid & 7) == 1) ? 1.0f : 0.0f;
    if (tid < SPB) S.bflow_s[tid] = g_baseflow[blk * SPB + tid];
    __syncthreads();

    const int bsample = blk * SPB + wid4;   // this warp's sample (tid<128)
    float xreg = 0.0f;
    if (tid < 128 && lane < 16) xreg = hyd[bsample * 17 + 1 + lane];

    for (int t = 0; t < STEPS; t++) {
        // ---- build layer-0 input [x_t, 0.01*stores] ----
        if (tid < 128) {
            if (lane < 16)      S.xin[lane * 4 + wid4] = xreg;
            else if (lane < 24) S.xin[lane * 4 + wid4] = 0.01f * S.st[wid4 * 8 + (lane - 16)];
            if (lane == 0)      S.rain_s[wid4] = xreg;   // rain = feature 0
        }
        __syncthreads();

        // prefetch next x (overlaps the whole step)
        if (tid < 128 && lane < 16 && t + 1 < STEPS)
            xreg = hyd[((t + 1) * BATCH + bsample) * 17 + 1 + lane];

        // ---- layer 0: 24 -> 128 (computed by both halves, half0 stores) ----
        {
            float bj = S.b0s[j];
            u64 a01 = pack2(bj, bj), a23 = a01;
            #pragma unroll
            for (int i = 0; i < 24; i++) {
                float w = S.w0t[i * 128 + j];
                u64 wd = pack2(w, w);
                ulonglong2 h = *(const ulonglong2*)&S.xin[i * 4];
                fma2(a01, h.x, wd); fma2(a23, h.y, wd);
            }
            if (half == 0) {
                float f0, f1, f2, f3;
                unpack2(a01, f0, f1); unpack2(a23, f2, f3);
                float4 hv = make_float4(fmaxf(f0, 0.f), fmaxf(f1, 0.f),
                                        fmaxf(f2, 0.f), fmaxf(f3, 0.f));
                *(float4*)&S.hA[j * 4] = hv;
            }
        }
        __syncthreads();

        // ---- layer 1 partial: half h reduces i in [h*64, h*64+64) ----
        {
            float bj = (half == 0) ? S.b1s[j] : 0.f;
            u64 a01 = pack2(bj, bj), a23 = a01;
            const float* hp = &S.hA[half * 64 * 4];
            #pragma unroll
            for (int k = 0; k < 64; k++) {
                u64 wd = pack2(w1r[k], w1r[k]);
                ulonglong2 h = *(const ulonglong2*)&hp[k * 4];
                fma2(a01, h.x, wd); fma2(a23, h.y, wd);
            }
            ulonglong2 pv; pv.x = a01; pv.y = a23;
            *(ulonglong2*)&S.part[half][j][0] = pv;
        }
        __syncthreads();

        // ---- combine layer 1 -> hB ----
        if (tid < 128) {
            ulonglong2 pa = *(const ulonglong2*)&S.part[0][tid][0];
            ulonglong2 pb = *(const ulonglong2*)&S.part[1][tid][0];
            u64 s01 = add2(pa.x, pb.x), s23 = add2(pa.y, pb.y);
            float f0, f1, f2, f3;
            unpack2(s01, f0, f1); unpack2(s23, f2, f3);
            float4 hv = make_float4(fmaxf(f0, 0.f), fmaxf(f1, 0.f),
                                    fmaxf(f2, 0.f), fmaxf(f3, 0.f));
            *(float4*)&S.hB[tid * 4] = hv;
        }
        __syncthreads();

        // ---- layer 2 partial: 128 -> 89 ----
        if (j < 89) {
            float bj = (half == 0) ? S.bcs[j] : 0.f;
            u64 a01 = pack2(bj, bj), a23 = a01;
            const float* hp = &S.hB[half * 64 * 4];
            #pragma unroll
            for (int k = 0; k < 64; k++) {
                u64 wd = pack2(wcr[k], wcr[k]);
                ulonglong2 h = *(const ulonglong2*)&hp[k * 4];
                fma2(a01, h.x, wd); fma2(a23, h.y, wd);
            }
            ulonglong2 pv; pv.x = a01; pv.y = a23;
            *(ulonglong2*)&S.part[half][j][0] = pv;
        }
        __syncthreads();

        // ---- epilogue: warps 0-3, sample wid4 (combine folded in) ----
        if (tid < 128) {
            float v0 = S.part[0][lane][wid4] + S.part[1][lane][wid4];       // j = lane
            int j1 = lane + 32, j2 = lane + 64;
            float v1 = S.part[0][j1][wid4] + S.part[1][j1][wid4];
            float v2g = (j2 < 89) ? S.part[0][j2][wid4] + S.part[1][j2][wid4] : 0.f;

            // softmax over logits j=0..8 (held in v0 of lanes 0..8)
            float logit = (lane < 9) ? v0 : -1e30f;
            float m = logit;
            #pragma unroll
            for (int off = 16; off > 0; off >>= 1)
                m = fmaxf(m, __shfl_xor_sync(0xffffffffu, m, off));
            float e = (lane < 9) ? expf(logit - m) : 0.f;
            float ssum = e;
            #pragma unroll
            for (int off = 16; off > 0; off >>= 1)
                ssum += __shfl_xor_sync(0xffffffffu, ssum, off);
            float aval = e / ssum;
            float rain = S.rain_s[wid4];
            if (lane >= 1 && lane < 9)
                S.st[wid4 * 8 + lane - 1] += aval * rain;   // stores += a[1:]*rain

            // sigmoids for gate cols (j>=9  <->  b-col j-9)
            if (lane >= 9)  S.outg[wid4][lane - 9] = 1.f / (1.f + expf(-v0));
            S.outg[wid4][j1 - 9] = 1.f / (1.f + expf(-v1));
            if (j2 < 89)    S.outg[wid4][j2 - 9] = 1.f / (1.f + expf(-v2g));
            __syncwarp();

            // serial mixing / escape / flow in lane 0 (register-resident)
            if (lane == 0) {
                const float* bb = S.outg[wid4];
                float* stp = &S.st[wid4 * 8];
                float sv[8];
                #pragma unroll
                for (int k = 0; k < 8; k++) sv[k] = stp[k];
                #pragma unroll
                for (int d = 0; d < 8; d++) {
                    float fb[8]; float fsum = 0.f;
                    #pragma unroll
                    for (int k = 0; k < 8; k++) { fb[k] = bb[d * 8 + k] * sv[k]; fsum += fb[k]; }
                    #pragma unroll
                    for (int k = 0; k < 8; k++) sv[k] -= fb[k];
                    sv[d] += fsum;
                }
                #pragma unroll
                for (int k = 0; k < 8; k++) sv[k] -= bb[64 + k] * sv[k];   // escape
                float flow = 0.f;
                #pragma unroll
                for (int k = 0; k < 8; k++) {
                    float fd = bb[72 + k] * sv[k];
                    flow += fd;
                    sv[k] -= fd;
                }
                out[t * BATCH + bsample] = flow;
                if (t == 0)
                    sv[2] = S.bflow_s[wid4] / fmaxf(bb[74], 1e-5f);  // b_flow[SLOW]
                #pragma unroll
                for (int k = 0; k < 8; k++) stp[k] = sv[k];
            }
        }
        __syncthreads();   // stores visible for next step
    }
}

// ---------------------------------------------------------------------------
// Harness entry.  Inputs: hyd_input, W0, b0, W1, b1, W_in, b_in, W_out, b_out
// ---------------------------------------------------------------------------
extern "C" void kernel_launch(void* const* d_in, const int* in_sizes, int n_in,
                              void* d_out, int out_size) {
    const float* hyd = (const float*)d_in[0];
    const float* W0  = (const float*)d_in[1];
    const float* b0  = (const float*)d_in[2];
    const float* W1  = (const float*)d_in[3];
    const float* b1  = (const float*)d_in[4];
    const float* Wi  = (const float*)d_in[5];
    const float* bi  = (const float*)d_in[6];
    const float* Wo  = (const float*)d_in[7];
    const float* bo  = (const float*)d_in[8];
    float* out = (float*)d_out;

    baseflow_kernel<<<BATCH, 1024>>>(hyd);
    hyd_kernel<<<NBLK, THREADS>>>(hyd, W0, b0, W1, b1, Wi, bi, Wo, bo, out);
}

// round 3
// speedup vs baseline: 2.6642x; 1.2039x over previous
#include <cuda_runtime.h>
#include <math.h>

#define STEPS 2048
#define BATCH 512
#define SPB   4
#define NBLK  (BATCH / SPB)   // 128 blocks -> one wave on 148 SMs
#define THREADS 512

typedef unsigned long long u64;

__device__ float g_baseflow[BATCH];

// ---------------------------------------------------------------------------
// packed f32x2 helpers
// ---------------------------------------------------------------------------
__device__ __forceinline__ u64 pack2(float lo, float hi) {
    u64 r; asm("mov.b64 %0, {%1, %2};" : "=l"(r) : "f"(lo), "f"(hi)); return r;
}
__device__ __forceinline__ void unpack2(u64 v, float& lo, float& hi) {
    asm("mov.b64 {%0, %1}, %2;" : "=f"(lo), "=f"(hi) : "l"(v));
}
__device__ __forceinline__ void fma2(u64& acc, u64 a, u64 b) {
    asm("fma.rn.f32x2 %0, %1, %2, %0;" : "+l"(acc) : "l"(a), "l"(b));
}
__device__ __forceinline__ u64 add2(u64 a, u64 b) {
    u64 r; asm("add.rn.f32x2 %0, %1, %2;" : "=l"(r) : "l"(a), "l"(b)); return r;
}
__device__ __forceinline__ float fast_sigmoid(float v) {
    return __fdividef(1.0f, 1.0f + __expf(-v));
}

// ---------------------------------------------------------------------------
// Kernel 1: per-batch-element 25th percentile of flow (bitonic sort)
// ---------------------------------------------------------------------------
__global__ void baseflow_kernel(const float* __restrict__ hyd) {
    __shared__ float v[STEPS];
    const int b = blockIdx.x;
    const int tid = threadIdx.x;
    for (int t = tid; t < STEPS; t += blockDim.x)
        v[t] = hyd[(t * BATCH + b) * 17];
    __syncthreads();
    for (int k = 2; k <= STEPS; k <<= 1) {
        for (int j = k >> 1; j > 0; j >>= 1) {
            for (int i = tid; i < STEPS; i += blockDim.x) {
                int l = i ^ j;
                if (l > i) {
                    float a = v[i], c = v[l];
                    bool up = ((i & k) == 0);
                    if ((a > c) == up) { v[i] = c; v[l] = a; }
                }
            }
            __syncthreads();
        }
    }
    if (tid == 0)
        g_baseflow[b] = 0.25f * v[511] + 0.75f * v[512];   // pos = 511.75
}

// ---------------------------------------------------------------------------
// Shared memory (~27 KB)
// ---------------------------------------------------------------------------
struct __align__(16) Smem {
    float w0t[24 * 128];        // W0 transposed [i][j]
    float b0s[128];
    float b1s[128];
    float bcs[96];              // [W_in;W_out] bias, padded
    float xin[24 * 4];          // layer-0 input [i][sample]
    float hA[128 * 4];          // layer-0 output [j][sample]
    float hB[128 * 4];          // layer-1 output
    float part[4][128][4];      // partials [quarter][j][sample]
    float outv[4][92];          // [sample][j]: j<9 raw logits, j>=9 sigmoided
    float st[4 * 8];            // stores state
    float rain_s[4];
    float bflow_s[4];
};

// ---------------------------------------------------------------------------
// Kernel 2: 512 threads = 16 warps (4/SMSP).
// j = tid&127 owns hidden/output unit j; q = tid>>7 owns a 32-slice of the
// reduction dim for layers 1/2. Warps 0-3 own one sample each for the
// epilogue. Layer 0 is sample-split across quarters 0/1 (no combine needed).
// Layer-2 combine + sigmoids run on 356 threads (spreads MUFU load).
// ---------------------------------------------------------------------------
__global__ void __launch_bounds__(THREADS, 1)
hyd_kernel(const float* __restrict__ hyd,
           const float* __restrict__ W0, const float* __restrict__ b0,
           const float* __restrict__ W1, const float* __restrict__ b1,
           const float* __restrict__ Wi, const float* __restrict__ bi,
           const float* __restrict__ Wo, const float* __restrict__ bo,
           float* __restrict__ out)
{
    __shared__ Smem S;
    const int tid  = threadIdx.x;
    const int j    = tid & 127;
    const int q    = tid >> 7;
    const int lane = tid & 31;
    const int w4   = (tid >> 5) & 3;   // sample index for tid<128
    const int blk  = blockIdx.x;

    // ---- register-resident weight slices (32 each for layers 1 and 2) ----
    float w1r[32], wcr[32];
    #pragma unroll
    for (int k = 0; k < 32; k++) w1r[k] = W1[j * 128 + q * 32 + k];
    if (j < 9) {
        #pragma unroll
        for (int k = 0; k < 32; k++) wcr[k] = Wi[j * 128 + q * 32 + k];
    } else if (j < 89) {
        #pragma unroll
        for (int k = 0; k < 32; k++) wcr[k] = Wo[(j - 9) * 128 + q * 32 + k];
    } else {
        #pragma unroll
        for (int k = 0; k < 32; k++) wcr[k] = 0.f;
    }

    // ---- SMEM init ----
    for (int idx = tid; idx < 24 * 128; idx += THREADS) {
        int i = idx >> 7, jj = idx & 127;
        S.w0t[idx] = W0[jj * 24 + i];
    }
    if (tid < 128) { S.b0s[tid] = b0[tid]; S.b1s[tid] = b1[tid]; }
    if (tid < 89)  S.bcs[tid] = (tid < 9) ? bi[tid] : bo[tid - 9];
    if (tid < 32)  S.st[tid] = ((tid & 7) == 1) ? 1.0f : 0.0f;
    if (tid < SPB) S.bflow_s[tid] = g_baseflow[blk * SPB + tid];

    const int bsample = blk * SPB + w4;     // warp w4's sample (tid<128)
    float xreg = 0.0f;
    if (tid < 128 && lane < 16) xreg = hyd[bsample * 17 + 1 + lane];

    // initial xin / rain for t=0
    if (tid < 128) {
        if (lane < 16)      S.xin[lane * 4 + w4] = xreg;
        else if (lane < 24) S.xin[lane * 4 + w4] = ((lane - 16) == 1) ? 0.01f : 0.f;
        if (lane == 0)      S.rain_s[w4] = xreg;
    }
    __syncthreads();   // barrier A (t=0)

    for (int t = 0; t < STEPS; t++) {
        // ---- layer 0: 24 -> 128, sample-split across quarters 0/1 ----
        if (q < 2) {
            float bj = S.b0s[j];
            u64 acc = pack2(bj, bj);     // samples 2q, 2q+1
            #pragma unroll
            for (int i = 0; i < 24; i++) {
                float w = S.w0t[i * 128 + j];
                u64 wd = pack2(w, w);
                u64 h  = *(const u64*)&S.xin[i * 4 + 2 * q];
                fma2(acc, h, wd);
            }
            float f0, f1;
            unpack2(acc, f0, f1);
            u64 hv = pack2(fmaxf(f0, 0.f), fmaxf(f1, 0.f));
            *(u64*)&S.hA[j * 4 + 2 * q] = hv;
        }
        // prefetch next step's x
        if (tid < 128 && lane < 16 && t + 1 < STEPS)
            xreg = hyd[((t + 1) * BATCH + bsample) * 17 + 1 + lane];
        __syncthreads();   // barrier B: hA ready

        // ---- layer 1 partial: quarter q reduces k in [32q, 32q+32) ----
        {
            float bj = (q == 0) ? S.b1s[j] : 0.f;
            u64 a01 = pack2(bj, bj), a23 = a01;
            const float* hp = &S.hA[q * 32 * 4];
            #pragma unroll
            for (int k = 0; k < 32; k++) {
                u64 wd = pack2(w1r[k], w1r[k]);
                ulonglong2 h = *(const ulonglong2*)&hp[k * 4];
                fma2(a01, h.x, wd); fma2(a23, h.y, wd);
            }
            ulonglong2 pv; pv.x = a01; pv.y = a23;
            *(ulonglong2*)&S.part[q][j][0] = pv;
        }
        __syncthreads();   // barrier D

        // ---- combine layer 1 -> hB (relu) ----
        if (tid < 128) {
            ulonglong2 p0 = *(const ulonglong2*)&S.part[0][tid][0];
            ulonglong2 p1 = *(const ulonglong2*)&S.part[1][tid][0];
            ulonglong2 p2 = *(const ulonglong2*)&S.part[2][tid][0];
            ulonglong2 p3 = *(const ulonglong2*)&S.part[3][tid][0];
            u64 s01 = add2(add2(p0.x, p1.x), add2(p2.x, p3.x));
            u64 s23 = add2(add2(p0.y, p1.y), add2(p2.y, p3.y));
            float f0, f1, f2, f3;
            unpack2(s01, f0, f1); unpack2(s23, f2, f3);
            float4 hv = make_float4(fmaxf(f0, 0.f), fmaxf(f1, 0.f),
                                    fmaxf(f2, 0.f), fmaxf(f3, 0.f));
            *(float4*)&S.hB[tid * 4] = hv;
        }
        __syncthreads();   // barrier E: hB ready

        // ---- layer 2 partial: 128 -> 89 ----
        if (j < 89) {
            float bj = (q == 0) ? S.bcs[j] : 0.f;
            u64 a01 = pack2(bj, bj), a23 = a01;
            const float* hp = &S.hB[q * 32 * 4];
            #pragma unroll
            for (int k = 0; k < 32; k++) {
                u64 wd = pack2(wcr[k], wcr[k]);
                ulonglong2 h = *(const ulonglong2*)&hp[k * 4];
                fma2(a01, h.x, wd); fma2(a23, h.y, wd);
            }
            ulonglong2 pv; pv.x = a01; pv.y = a23;
            *(ulonglong2*)&S.part[q][j][0] = pv;
        }
        __syncthreads();   // barrier F

        // ---- combine layer 2 + sigmoid (356 threads; spreads MUFU) ----
        if (tid < 356) {
            int s  = tid & 3;
            int jj = tid >> 2;
            float v = S.part[0][jj][s] + S.part[1][jj][s]
                    + S.part[2][jj][s] + S.part[3][jj][s];
            S.outv[s][jj] = (jj < 9) ? v : fast_sigmoid(v);
        }
        __syncthreads();   // barrier G

        // ---- epilogue: warps 0-3, one sample each ----
        if (tid < 128) {
            // softmax over 9 logits, 16-wide reductions
            float logit = (lane < 9) ? S.outv[w4][lane] : -1e30f;
            float m = logit;
            #pragma unroll
            for (int off = 8; off > 0; off >>= 1)
                m = fmaxf(m, __shfl_xor_sync(0xffffffffu, m, off, 16));
            float e = (lane < 9) ? __expf(logit - m) : 0.f;
            float ssum = e;
            #pragma unroll
            for (int off = 8; off > 0; off >>= 1)
                ssum += __shfl_xor_sync(0xffffffffu, ssum, off, 16);
            float aval = __fdividef(e, ssum);
            float rain = S.rain_s[w4];
            if (lane >= 1 && lane < 9)
                S.st[w4 * 8 + lane - 1] += aval * rain;   // stores += a[1:]*rain
            __syncwarp();

            // serial mixing / escape / flow in lane 0
            if (lane == 0) {
                const float* bb = &S.outv[w4][9];
                float* stp = &S.st[w4 * 8];
                float sv[8];
                #pragma unroll
                for (int k = 0; k < 8; k++) sv[k] = stp[k];
                #pragma unroll
                for (int d = 0; d < 8; d++) {
                    float fb[8]; float fsum = 0.f;
                    #pragma unroll
                    for (int k = 0; k < 8; k++) { fb[k] = bb[d * 8 + k] * sv[k]; fsum += fb[k]; }
                    #pragma unroll
                    for (int k = 0; k < 8; k++) sv[k] -= fb[k];
                    sv[d] += fsum;
                }
                #pragma unroll
                for (int k = 0; k < 8; k++) sv[k] -= bb[64 + k] * sv[k];   // escape
                float flow = 0.f;
                #pragma unroll
                for (int k = 0; k < 8; k++) {
                    float fd = bb[72 + k] * sv[k];
                    flow += fd;
                    sv[k] -= fd;
                }
                out[t * BATCH + bsample] = flow;
                if (t == 0)
                    sv[2] = S.bflow_s[w4] / fmaxf(bb[74], 1e-5f);   // b_flow[SLOW]
                #pragma unroll
                for (int k = 0; k < 8; k++) {
                    stp[k] = sv[k];
                    S.xin[(16 + k) * 4 + w4] = 0.01f * sv[k];   // next-step input
                }
                S.rain_s[w4] = xreg;                            // next-step rain
            }
            if (lane < 16) S.xin[lane * 4 + w4] = xreg;          // next-step x
        }
        __syncthreads();   // barrier A (next step)
    }
}

// ---------------------------------------------------------------------------
// Harness entry.  Inputs: hyd_input, W0, b0, W1, b1, W_in, b_in, W_out, b_out
// ---------------------------------------------------------------------------
extern "C" void kernel_launch(void* const* d_in, const int* in_sizes, int n_in,
                              void* d_out, int out_size) {
    const float* hyd = (const float*)d_in[0];
    const float* W0  = (const float*)d_in[1];
    const float* b0  = (const float*)d_in[2];
    const float* W1  = (const float*)d_in[3];
    const float* b1  = (const float*)d_in[4];
    const float* Wi  = (const float*)d_in[5];
    const float* bi  = (const float*)d_in[6];
    const float* Wo  = (const float*)d_in[7];
    const float* bo  = (const float*)d_in[8];
    float* out = (float*)d_out;

    baseflow_kernel<<<BATCH, 1024>>>(hyd);
    hyd_kernel<<<NBLK, THREADS>>>(hyd, W0, b0, W1, b1, Wi, bi, Wo, bo, out);
}